// round 1
// baseline (speedup 1.0000x reference)
#include <cuda_runtime.h>
#include <math.h>

#define N 512
#define D 128
#define DEPTH 4
#define TT 16          // tokens per layer-kernel tile
#define SC 128         // s-chunk size
#define NTILE (N/TT)   // 32
#define NSC (N/SC)     // 4

// ---------------- scratch (device globals; no allocation allowed) ----------------
__device__ float g_q[N*D];
__device__ float g_lr[N], g_am[N], g_dk[N];          // lr, momentum coeff, (1-decay)
__device__ float g_A[DEPTH*N*D];                     // layer inputs  a_i(s)
__device__ float g_G[DEPTH*N*D];                     // layer out-grads g_i(s)
__device__ float g_WT[DEPTH*D*D];                    // W_mem transposed per layer
__device__ float g_Chat[N*N];                        // Chat[t][s] = C(s,t)*(-lr[s]), 0 above diag
__device__ float g_Yp0[NSC*N*D];                     // partial-Y ping
__device__ float g_Yp1[NSC*N*D];                     // partial-Y pong

__device__ __forceinline__ float siluf(float z){
    float s = 1.f/(1.f+__expf(-z));
    return z*s;
}
__device__ __forceinline__ float dsiluf(float z){
    float s = 1.f/(1.f+__expf(-z));
    return s*(1.f + z*(1.f-s));
}

// ---------------- transpose W_mem ----------------
__global__ void tr_kernel(const float* __restrict__ Wmem){
    int l = blockIdx.x;
    for (int e = threadIdx.x; e < D*D; e += blockDim.x){
        int j = e >> 7, i = e & 127;           // e = j*128 + i
        g_WT[l*D*D + e] = Wmem[l*D*D + i*D + j];
    }
}

// ---------------- per-token: scalars, q/k/v, MLP fwd+bwd -> A, G ----------------
__global__ void token_kernel(const float* __restrict__ seq,
                             const float* __restrict__ Wmem,
                             const float* __restrict__ Wq,
                             const float* __restrict__ Wkv,
                             const float* __restrict__ Wmom,
                             const float* __restrict__ Wstep,
                             const float* __restrict__ Wdecay){
    int t = blockIdx.x;
    int j = threadIdx.x;
    __shared__ float sx[D], sk[D], sv[D], s1[D], s2[D], s3[D], sg[D];
    __shared__ float red[3][4];

    float x = seq[t*D + j];
    sx[j] = x;

    // scalar reductions: lr, am, decay
    float p0 = x*Wstep[j], p1 = x*Wmom[j], p2 = x*Wdecay[j];
    #pragma unroll
    for (int o = 16; o > 0; o >>= 1){
        p0 += __shfl_xor_sync(0xffffffffu, p0, o);
        p1 += __shfl_xor_sync(0xffffffffu, p1, o);
        p2 += __shfl_xor_sync(0xffffffffu, p2, o);
    }
    if ((j & 31) == 0){ red[0][j>>5]=p0; red[1][j>>5]=p1; red[2][j>>5]=p2; }
    __syncthreads();
    if (j == 0){
        g_lr[t] = red[0][0]+red[0][1]+red[0][2]+red[0][3];
        g_am[t] = red[1][0]+red[1][1]+red[1][2]+red[1][3];
        float dz = red[2][0]+red[2][1]+red[2][2]+red[2][3];
        g_dk[t] = 1.f - 1.f/(1.f+__expf(-dz));
    }

    // q, k, v
    float qa = 0.f, ka = 0.f, va = 0.f;
    #pragma unroll 4
    for (int i = 0; i < D; i++){
        float xi = sx[i];
        qa += xi*Wq[i*D + j];
        ka += xi*Wkv[i*2*D + j];
        va += xi*Wkv[i*2*D + D + j];
    }
    g_q[t*D + j] = qa;
    sk[j] = ka; sv[j] = va;
    g_A[0*N*D + t*D + j] = ka;                  // a_0 = k
    __syncthreads();

    // forward through W_mem
    float z1 = 0.f;
    #pragma unroll 4
    for (int i = 0; i < D; i++) z1 += sk[i]*Wmem[0*D*D + i*D + j];
    float x1 = siluf(z1); s1[j] = x1; g_A[1*N*D + t*D + j] = x1;
    __syncthreads();
    float z2 = 0.f;
    #pragma unroll 4
    for (int i = 0; i < D; i++) z2 += s1[i]*Wmem[1*D*D + i*D + j];
    float x2 = siluf(z2); s2[j] = x2; g_A[2*N*D + t*D + j] = x2;
    __syncthreads();
    float z3 = 0.f;
    #pragma unroll 4
    for (int i = 0; i < D; i++) z3 += s2[i]*Wmem[2*D*D + i*D + j];
    float x3 = siluf(z3); s3[j] = x3; g_A[3*N*D + t*D + j] = x3;
    __syncthreads();
    float z4 = 0.f;
    #pragma unroll 4
    for (int i = 0; i < D; i++) z4 += s3[i]*Wmem[3*D*D + i*D + j];

    // backward: g_i = dL/dz_{i+1}
    float gg = (z4 - sv[j]) * (2.f/(float)D);
    g_G[3*N*D + t*D + j] = gg; sg[j] = gg;
    __syncthreads();
    float dx = 0.f;
    #pragma unroll 4
    for (int m = 0; m < D; m++) dx += sg[m]*g_WT[3*D*D + m*D + j];
    gg = dx * dsiluf(z3);
    g_G[2*N*D + t*D + j] = gg;
    __syncthreads(); sg[j] = gg; __syncthreads();
    dx = 0.f;
    #pragma unroll 4
    for (int m = 0; m < D; m++) dx += sg[m]*g_WT[2*D*D + m*D + j];
    gg = dx * dsiluf(z2);
    g_G[1*N*D + t*D + j] = gg;
    __syncthreads(); sg[j] = gg; __syncthreads();
    dx = 0.f;
    #pragma unroll 4
    for (int m = 0; m < D; m++) dx += sg[m]*g_WT[1*D*D + m*D + j];
    gg = dx * dsiluf(z1);
    g_G[0*N*D + t*D + j] = gg;
}

// ---------------- scan-coefficient matrix ----------------
// Chat[t][s] = (-lr[s]) * C(s,t);  C(s,t) = dk_t*C(s,t-1) + M(s,t), M(s,t)=M(s,t-1)*am_t, M(s,s)=1
__global__ void chat_kernel(){
    int s = threadIdx.x;             // 512 threads, one per source token
    float m = 0.f, c = 0.f;
    float nl = -g_lr[s];
    for (int t = 0; t < N; t++){
        float out;
        if (t < s) out = 0.f;
        else if (t == s){ m = 1.f; c = 1.f; out = nl; }
        else {
            m *= g_am[t];
            c = g_dk[t]*c + m;
            out = nl*c;
        }
        g_Chat[t*N + s] = out;
    }
}

// ---------------- fused attention layer ----------------
// Y = X @ W_l + (Chat ⊙ (X @ A_lᵀ)) @ G_l, written as per-(s-chunk) partials (no atomics).
// srcSel: 0 -> g_q (no silu, direct) ; 1 -> g_Yp0 parts+silu, dst g_Yp1 ; 2 -> g_Yp1 parts+silu, dst g_Yp0
__global__ __launch_bounds__(256) void layer_kernel(const float* __restrict__ Wmem,
                                                    int layer, int srcSel){
    extern __shared__ float sm[];
    float* XsT = sm;                       // [D][TT]  XsT[i*TT+tt]
    float* As  = sm + D*TT;                // [SC][D+1] (A chunk, later reused for G chunk)
    float* PsT = As + SC*(D+1);            // [SC][TT]

    int t0 = blockIdx.x*TT, s0 = blockIdx.y*SC;
    if (s0 > t0 + TT - 1) return;

    const float* Xsrc; float* Ydst; int partSrc;
    if      (srcSel == 0){ Xsrc = g_q;   Ydst = g_Yp0; partSrc = 0; }
    else if (srcSel == 1){ Xsrc = g_Yp0; Ydst = g_Yp1; partSrc = 1; }
    else                 { Xsrc = g_Yp1; Ydst = g_Yp0; partSrc = 1; }

    const float* W  = Wmem + layer*D*D;
    const float* Al = g_A  + layer*N*D;
    const float* Gl = g_G  + layer*N*D;

    int tid  = threadIdx.x;
    int lane = tid & 127;        // ss in dot phase, j in accum phase
    int g    = tid >> 7;         // half: tt range [g*8, g*8+8)

    // load X tile (sum previous-layer partial slices + silu if needed), store transposed
    int cnt = (t0 + TT - 1)/SC + 1;       // part slices valid for this t-tile (prev layer, same tiling)
    for (int e = tid; e < TT*D; e += 256){
        int tt = e >> 7, i = e & 127;
        int t = t0 + tt;
        float x;
        if (!partSrc) x = Xsrc[t*D + i];
        else {
            float a = 0.f;
            for (int c = 0; c < cnt; c++) a += Xsrc[(c*N + t)*D + i];
            x = siluf(a);
        }
        XsT[i*TT + tt] = x;
    }
    // load A chunk
    for (int e = tid; e < SC*D; e += 256){
        int r = e >> 7, cc = e & 127;
        As[r*(D+1) + cc] = Al[(s0 + r)*D + cc];
    }
    __syncthreads();

    // dots: P[tt][ss] = Chat[t][s] * (x_t · a_s)
    float dac[8];
    #pragma unroll
    for (int k = 0; k < 8; k++) dac[k] = 0.f;
    const float* arow = As + lane*(D+1);
    #pragma unroll 4
    for (int i = 0; i < D; i++){
        float av = arow[i];
        float4 xa = *reinterpret_cast<const float4*>(&XsT[i*TT + g*8]);
        float4 xb = *reinterpret_cast<const float4*>(&XsT[i*TT + g*8 + 4]);
        dac[0] += av*xa.x; dac[1] += av*xa.y; dac[2] += av*xa.z; dac[3] += av*xa.w;
        dac[4] += av*xb.x; dac[5] += av*xb.y; dac[6] += av*xb.z; dac[7] += av*xb.w;
    }
    int s = s0 + lane;
    #pragma unroll
    for (int k = 0; k < 8; k++){
        int t = t0 + g*8 + k;
        PsT[lane*TT + g*8 + k] = dac[k] * g_Chat[t*N + s];   // Chat is 0 above diagonal
    }
    __syncthreads();

    // reload smem with G chunk
    for (int e = tid; e < SC*D; e += 256){
        int r = e >> 7, cc = e & 127;
        As[r*(D+1) + cc] = Gl[(s0 + r)*D + cc];
    }
    __syncthreads();

    // accumulate Y[tt][j] = (sc==0 ? x·W[:,j] : 0) + sum_ss P[tt][ss]*G[ss][j]
    float acc[8];
    #pragma unroll
    for (int k = 0; k < 8; k++) acc[k] = 0.f;

    if (s0 == 0){
        #pragma unroll 2
        for (int i = 0; i < D; i++){
            float w = W[i*D + lane];
            float4 xa = *reinterpret_cast<const float4*>(&XsT[i*TT + g*8]);
            float4 xb = *reinterpret_cast<const float4*>(&XsT[i*TT + g*8 + 4]);
            acc[0] += w*xa.x; acc[1] += w*xa.y; acc[2] += w*xa.z; acc[3] += w*xa.w;
            acc[4] += w*xb.x; acc[5] += w*xb.y; acc[6] += w*xb.z; acc[7] += w*xb.w;
        }
    }
    #pragma unroll 2
    for (int ssn = 0; ssn < SC; ssn++){
        float gv = As[ssn*(D+1) + lane];
        float4 pa = *reinterpret_cast<const float4*>(&PsT[ssn*TT + g*8]);
        float4 pb = *reinterpret_cast<const float4*>(&PsT[ssn*TT + g*8 + 4]);
        acc[0] += gv*pa.x; acc[1] += gv*pa.y; acc[2] += gv*pa.z; acc[3] += gv*pa.w;
        acc[4] += gv*pb.x; acc[5] += gv*pb.y; acc[6] += gv*pb.z; acc[7] += gv*pb.w;
    }
    #pragma unroll
    for (int k = 0; k < 8; k++){
        int t = t0 + g*8 + k;
        Ydst[((int)blockIdx.y*N + t)*D + lane] = acc[k];
    }
}

// ---------------- sum final partials into d_out (no silu on last layer) ----------------
__global__ void finalize_kernel(float* __restrict__ out){
    int e = blockIdx.x*blockDim.x + threadIdx.x;   // 0..N*D-1
    int t = e >> 7;
    int cnt = ((t/TT)*TT + TT - 1)/SC + 1;
    float a = 0.f;
    for (int c = 0; c < cnt; c++) a += g_Yp1[(c*N + t)*D + (e & 127)];
    out[e] = a;
}

// ---------------- launch ----------------
extern "C" void kernel_launch(void* const* d_in, const int* in_sizes, int n_in,
                              void* d_out, int out_size){
    const float* seq    = (const float*)d_in[0];
    const float* Wmem   = (const float*)d_in[1];
    const float* Wq     = (const float*)d_in[2];
    const float* Wkv    = (const float*)d_in[3];
    const float* Wmom   = (const float*)d_in[4];
    const float* Wstep  = (const float*)d_in[5];
    const float* Wdecay = (const float*)d_in[6];
    float* out = (float*)d_out;

    size_t smem = (size_t)(D*TT + SC*(D+1) + SC*TT)*sizeof(float);   // 82432 B
    cudaFuncSetAttribute(layer_kernel, cudaFuncAttributeMaxDynamicSharedMemorySize, (int)smem);

    tr_kernel<<<DEPTH, 128>>>(Wmem);
    token_kernel<<<N, D>>>(seq, Wmem, Wq, Wkv, Wmom, Wstep, Wdecay);
    chat_kernel<<<1, N>>>();

    dim3 lg(NTILE, NSC);
    layer_kernel<<<lg, 256, smem>>>(Wmem, 0, 0);   // q      -> Yp0
    layer_kernel<<<lg, 256, smem>>>(Wmem, 1, 1);   // Yp0    -> Yp1
    layer_kernel<<<lg, 256, smem>>>(Wmem, 2, 2);   // Yp1    -> Yp0
    layer_kernel<<<lg, 256, smem>>>(Wmem, 3, 1);   // Yp0    -> Yp1
    finalize_kernel<<<(N*D)/256, 256>>>(out);
}

// round 2
// speedup vs baseline: 1.5742x; 1.5742x over previous
#include <cuda_runtime.h>
#include <math.h>

#define N 512
#define D 128
#define DEPTH 4
#define TT 32            // tokens per layer tile
#define SC 64            // s-chunk size
#define NA (N/TT)        // 16 t-tiles
#define NB (N/SC)        // 8 real s-chunks
#define NSLICE 10        // 8 real + 2 W-chunks
#define XS_STRIDE 132
#define PS_STRIDE 68

// ---------------- scratch ----------------
__device__ float g_q[N*D];
__device__ float g_lr[N], g_am[N], g_dk[N];
__device__ float g_A[DEPTH*N*D];
__device__ float g_G[DEPTH*N*D];
__device__ float g_WT[DEPTH*D*D];
__device__ float g_Chat[N*N];
__device__ float g_Yp0[NSLICE*N*D];
__device__ float g_Yp1[NSLICE*N*D];

__device__ __forceinline__ float siluf(float z){
    float s = 1.f/(1.f+__expf(-z));
    return z*s;
}
__device__ __forceinline__ float dsiluf(float z){
    float s = 1.f/(1.f+__expf(-z));
    return s*(1.f + z*(1.f-s));
}

// ---------------- transpose W_mem ----------------
__global__ void tr_kernel(const float* __restrict__ Wmem){
    int l = blockIdx.x;
    for (int e = threadIdx.x; e < D*D; e += blockDim.x){
        int j = e >> 7, i = e & 127;
        g_WT[l*D*D + e] = Wmem[l*D*D + i*D + j];
    }
}

// ---------------- per-token MLP fwd+bwd, 4 tokens per block ----------------
__global__ __launch_bounds__(128) void token_kernel(const float* __restrict__ seq,
                             const float* __restrict__ Wmem,
                             const float* __restrict__ Wq,
                             const float* __restrict__ Wkv,
                             const float* __restrict__ Wmom,
                             const float* __restrict__ Wstep,
                             const float* __restrict__ Wdecay){
    int t0 = blockIdx.x*4;
    int j = threadIdx.x;
    __shared__ float sx[4][D];
    __shared__ float sA[4][D];
    __shared__ float sB[4][D];
    __shared__ float sv[4][D];
    __shared__ float red[12][4];

    #pragma unroll
    for (int m = 0; m < 4; m++) sx[m][j] = seq[(t0+m)*D + j];

    // per-token scalars
    {
        float ws = Wstep[j], wm = Wmom[j], wd = Wdecay[j];
        #pragma unroll
        for (int m = 0; m < 4; m++){
            float xv = sx[m][j];
            float p0 = xv*ws, p1 = xv*wm, p2 = xv*wd;
            #pragma unroll
            for (int o = 16; o > 0; o >>= 1){
                p0 += __shfl_xor_sync(0xffffffffu, p0, o);
                p1 += __shfl_xor_sync(0xffffffffu, p1, o);
                p2 += __shfl_xor_sync(0xffffffffu, p2, o);
            }
            if ((j & 31) == 0){ red[m*3+0][j>>5]=p0; red[m*3+1][j>>5]=p1; red[m*3+2][j>>5]=p2; }
        }
    }
    __syncthreads();
    if (j < 4){
        g_lr[t0+j] = red[j*3+0][0]+red[j*3+0][1]+red[j*3+0][2]+red[j*3+0][3];
        g_am[t0+j] = red[j*3+1][0]+red[j*3+1][1]+red[j*3+1][2]+red[j*3+1][3];
        float dz = red[j*3+2][0]+red[j*3+2][1]+red[j*3+2][2]+red[j*3+2][3];
        g_dk[t0+j] = 1.f - 1.f/(1.f+__expf(-dz));
    }

    // q, k, v (weight LDG reused across 4 tokens)
    {
        float qa[4]={0,0,0,0}, ka[4]={0,0,0,0}, va[4]={0,0,0,0};
        for (int i = 0; i < D; i += 4){
            float4 xm[4];
            #pragma unroll
            for (int m = 0; m < 4; m++) xm[m] = *reinterpret_cast<const float4*>(&sx[m][i]);
            #pragma unroll
            for (int ii = 0; ii < 4; ii++){
                float wqv = Wq[(i+ii)*D + j];
                float wkv = Wkv[(i+ii)*2*D + j];
                float wvv = Wkv[(i+ii)*2*D + D + j];
                #pragma unroll
                for (int m = 0; m < 4; m++){
                    float xv = (ii==0)?xm[m].x:(ii==1)?xm[m].y:(ii==2)?xm[m].z:xm[m].w;
                    qa[m] += xv*wqv; ka[m] += xv*wkv; va[m] += xv*wvv;
                }
            }
        }
        #pragma unroll
        for (int m = 0; m < 4; m++){
            g_q[(t0+m)*D + j] = qa[m];
            g_A[0*N*D + (t0+m)*D + j] = ka[m];
            sA[m][j] = ka[m]; sv[m][j] = va[m];
        }
    }
    __syncthreads();

    float z1[4], z2[4], z3[4];
    // fwd stage macro-ish
    {   // z1 = k @ W0 ; x1 -> sB
        float z[4]={0,0,0,0};
        for (int i = 0; i < D; i += 4){
            float4 xm[4];
            #pragma unroll
            for (int m = 0; m < 4; m++) xm[m] = *reinterpret_cast<const float4*>(&sA[m][i]);
            #pragma unroll
            for (int ii = 0; ii < 4; ii++){
                float w = Wmem[0*D*D + (i+ii)*D + j];
                #pragma unroll
                for (int m = 0; m < 4; m++){
                    float xv = (ii==0)?xm[m].x:(ii==1)?xm[m].y:(ii==2)?xm[m].z:xm[m].w;
                    z[m] += xv*w;
                }
            }
        }
        #pragma unroll
        for (int m = 0; m < 4; m++){
            z1[m]=z[m]; float x1=siluf(z[m]);
            sB[m][j]=x1; g_A[1*N*D + (t0+m)*D + j]=x1;
        }
    }
    __syncthreads();
    {   // z2 = x1 @ W1 ; x2 -> sA
        float z[4]={0,0,0,0};
        for (int i = 0; i < D; i += 4){
            float4 xm[4];
            #pragma unroll
            for (int m = 0; m < 4; m++) xm[m] = *reinterpret_cast<const float4*>(&sB[m][i]);
            #pragma unroll
            for (int ii = 0; ii < 4; ii++){
                float w = Wmem[1*D*D + (i+ii)*D + j];
                #pragma unroll
                for (int m = 0; m < 4; m++){
                    float xv = (ii==0)?xm[m].x:(ii==1)?xm[m].y:(ii==2)?xm[m].z:xm[m].w;
                    z[m] += xv*w;
                }
            }
        }
        #pragma unroll
        for (int m = 0; m < 4; m++){
            z2[m]=z[m]; float x2=siluf(z[m]);
            sA[m][j]=x2; g_A[2*N*D + (t0+m)*D + j]=x2;
        }
    }
    __syncthreads();
    {   // z3 = x2 @ W2 ; x3 -> sB
        float z[4]={0,0,0,0};
        for (int i = 0; i < D; i += 4){
            float4 xm[4];
            #pragma unroll
            for (int m = 0; m < 4; m++) xm[m] = *reinterpret_cast<const float4*>(&sA[m][i]);
            #pragma unroll
            for (int ii = 0; ii < 4; ii++){
                float w = Wmem[2*D*D + (i+ii)*D + j];
                #pragma unroll
                for (int m = 0; m < 4; m++){
                    float xv = (ii==0)?xm[m].x:(ii==1)?xm[m].y:(ii==2)?xm[m].z:xm[m].w;
                    z[m] += xv*w;
                }
            }
        }
        #pragma unroll
        for (int m = 0; m < 4; m++){
            z3[m]=z[m]; float x3=siluf(z[m]);
            sB[m][j]=x3; g_A[3*N*D + (t0+m)*D + j]=x3;
        }
    }
    __syncthreads();
    {   // z4 = x3 @ W3 ; g3 = (z4 - v)*2/D -> sA, g_G[3]
        float z[4]={0,0,0,0};
        for (int i = 0; i < D; i += 4){
            float4 xm[4];
            #pragma unroll
            for (int m = 0; m < 4; m++) xm[m] = *reinterpret_cast<const float4*>(&sB[m][i]);
            #pragma unroll
            for (int ii = 0; ii < 4; ii++){
                float w = Wmem[3*D*D + (i+ii)*D + j];
                #pragma unroll
                for (int m = 0; m < 4; m++){
                    float xv = (ii==0)?xm[m].x:(ii==1)?xm[m].y:(ii==2)?xm[m].z:xm[m].w;
                    z[m] += xv*w;
                }
            }
        }
        #pragma unroll
        for (int m = 0; m < 4; m++){
            float gg = (z[m] - sv[m][j]) * (2.f/(float)D);
            sA[m][j]=gg; g_G[3*N*D + (t0+m)*D + j]=gg;
        }
    }
    __syncthreads();
    {   // dx = g3 @ W3^T ; g2 = dx*dsilu(z3) -> sB, g_G[2]
        float z[4]={0,0,0,0};
        for (int i = 0; i < D; i += 4){
            float4 xm[4];
            #pragma unroll
            for (int m = 0; m < 4; m++) xm[m] = *reinterpret_cast<const float4*>(&sA[m][i]);
            #pragma unroll
            for (int ii = 0; ii < 4; ii++){
                float w = g_WT[3*D*D + (i+ii)*D + j];
                #pragma unroll
                for (int m = 0; m < 4; m++){
                    float xv = (ii==0)?xm[m].x:(ii==1)?xm[m].y:(ii==2)?xm[m].z:xm[m].w;
                    z[m] += xv*w;
                }
            }
        }
        #pragma unroll
        for (int m = 0; m < 4; m++){
            float gg = z[m]*dsiluf(z3[m]);
            sB[m][j]=gg; g_G[2*N*D + (t0+m)*D + j]=gg;
        }
    }
    __syncthreads();
    {   // dx = g2 @ W2^T ; g1 = dx*dsilu(z2) -> sA, g_G[1]
        float z[4]={0,0,0,0};
        for (int i = 0; i < D; i += 4){
            float4 xm[4];
            #pragma unroll
            for (int m = 0; m < 4; m++) xm[m] = *reinterpret_cast<const float4*>(&sB[m][i]);
            #pragma unroll
            for (int ii = 0; ii < 4; ii++){
                float w = g_WT[2*D*D + (i+ii)*D + j];
                #pragma unroll
                for (int m = 0; m < 4; m++){
                    float xv = (ii==0)?xm[m].x:(ii==1)?xm[m].y:(ii==2)?xm[m].z:xm[m].w;
                    z[m] += xv*w;
                }
            }
        }
        #pragma unroll
        for (int m = 0; m < 4; m++){
            float gg = z[m]*dsiluf(z2[m]);
            sA[m][j]=gg; g_G[1*N*D + (t0+m)*D + j]=gg;
        }
    }
    __syncthreads();
    {   // dx = g1 @ W1^T ; g0 = dx*dsilu(z1) -> g_G[0]
        float z[4]={0,0,0,0};
        for (int i = 0; i < D; i += 4){
            float4 xm[4];
            #pragma unroll
            for (int m = 0; m < 4; m++) xm[m] = *reinterpret_cast<const float4*>(&sA[m][i]);
            #pragma unroll
            for (int ii = 0; ii < 4; ii++){
                float w = g_WT[1*D*D + (i+ii)*D + j];
                #pragma unroll
                for (int m = 0; m < 4; m++){
                    float xv = (ii==0)?xm[m].x:(ii==1)?xm[m].y:(ii==2)?xm[m].z:xm[m].w;
                    z[m] += xv*w;
                }
            }
        }
        #pragma unroll
        for (int m = 0; m < 4; m++)
            g_G[0*N*D + (t0+m)*D + j] = z[m]*dsiluf(z1[m]);
    }
}

// ---------------- scan-coefficient matrix ----------------
__global__ void chat_kernel(){
    __shared__ float sam[N], sdk[N];
    int s = threadIdx.x;
    sam[s] = g_am[s]; sdk[s] = g_dk[s];
    __syncthreads();
    float m = 0.f, c = 0.f;
    float nl = -g_lr[s];
    for (int t = 0; t < N; t++){
        float out;
        if (t < s) out = 0.f;
        else if (t == s){ m = 1.f; c = 1.f; out = nl; }
        else {
            m *= sam[t];
            c = sdk[t]*c + m;
            out = nl*c;
        }
        g_Chat[t*N + s] = out;
    }
}

// ---------------- fused attention layer ----------------
// grid (16, 10): b<8 -> real s-chunk; b>=8 -> W-chunk (P = X columns, G = W rows)
__global__ __launch_bounds__(256) void layer_kernel(const float* __restrict__ Wmem,
                                                    int layer, int srcSel){
    extern __shared__ float sm[];
    float* Xs = sm;                         // [32][132]
    float* As = Xs + TT*XS_STRIDE;          // [64][132]
    float* Gs = As + SC*XS_STRIDE;          // [64][132]
    float* Ps = Gs + SC*XS_STRIDE;          // [32][68]

    int a = blockIdx.x, b = blockIdx.y;
    int t0 = a*TT;
    bool isW = (b >= NB);
    int s0 = isW ? 0 : b*SC;
    if (!isW && s0 > t0 + TT - 1) return;

    const float* Xsrc; float* Ydst; int partSrc;
    if      (srcSel == 0){ Xsrc = g_q;   Ydst = g_Yp0; partSrc = 0; }
    else if (srcSel == 1){ Xsrc = g_Yp0; Ydst = g_Yp1; partSrc = 1; }
    else                 { Xsrc = g_Yp1; Ydst = g_Yp0; partSrc = 1; }

    const float* Al = g_A + layer*N*D;
    const float* Gl = g_G + layer*N*D;
    const float* Wl = Wmem + layer*D*D;

    int tid = threadIdx.x;
    int tx = tid & 31, ty = tid >> 5;

    // ---- load X tile (sum prev-layer partial slices + silu) ----
    int rb = (a >> 1) + 1;   // real slices present for this t-tile
    for (int e = tid; e < TT*D/4; e += 256){
        int t = e >> 5, k4 = (e & 31)*4;
        float4 v;
        if (!partSrc){
            v = *reinterpret_cast<const float4*>(&Xsrc[(t0+t)*D + k4]);
        } else {
            float4 acc = *reinterpret_cast<const float4*>(&Xsrc[(8*N + t0+t)*D + k4]);
            float4 w9  = *reinterpret_cast<const float4*>(&Xsrc[(9*N + t0+t)*D + k4]);
            acc.x += w9.x; acc.y += w9.y; acc.z += w9.z; acc.w += w9.w;
            for (int c = 0; c < rb; c++){
                float4 p = *reinterpret_cast<const float4*>(&Xsrc[(c*N + t0+t)*D + k4]);
                acc.x += p.x; acc.y += p.y; acc.z += p.z; acc.w += p.w;
            }
            v.x = siluf(acc.x); v.y = siluf(acc.y); v.z = siluf(acc.z); v.w = siluf(acc.w);
        }
        *reinterpret_cast<float4*>(&Xs[t*XS_STRIDE + k4]) = v;
    }
    // ---- load A and G chunks (real) or W rows (W-chunk) ----
    if (!isW){
        for (int e = tid; e < SC*32; e += 256){
            int r = e >> 5, k4 = (e & 31)*4;
            *reinterpret_cast<float4*>(&As[r*XS_STRIDE + k4]) =
                *reinterpret_cast<const float4*>(&Al[(s0+r)*D + k4]);
        }
        for (int e = tid; e < SC*32; e += 256){
            int r = e >> 5, k4 = (e & 31)*4;
            *reinterpret_cast<float4*>(&Gs[r*XS_STRIDE + k4]) =
                *reinterpret_cast<const float4*>(&Gl[(s0+r)*D + k4]);
        }
    } else {
        int w0 = (b - NB)*SC;
        for (int e = tid; e < SC*32; e += 256){
            int r = e >> 5, k4 = (e & 31)*4;
            *reinterpret_cast<float4*>(&Gs[r*XS_STRIDE + k4]) =
                *reinterpret_cast<const float4*>(&Wl[(w0+r)*D + k4]);
        }
    }
    __syncthreads();

    // ---- phase 1 (real chunks): S = (X @ A^T) ⊙ Chat -> Ps ----
    if (!isW){
        float c01[4][2];
        #pragma unroll
        for (int i = 0; i < 4; i++){ c01[i][0]=0.f; c01[i][1]=0.f; }
        #pragma unroll 4
        for (int k0 = 0; k0 < D; k0 += 4){
            float4 xv[4], av[2];
            #pragma unroll
            for (int i = 0; i < 4; i++)
                xv[i] = *reinterpret_cast<const float4*>(&Xs[(ty*4+i)*XS_STRIDE + k0]);
            #pragma unroll
            for (int jj = 0; jj < 2; jj++)
                av[jj] = *reinterpret_cast<const float4*>(&As[(tx+32*jj)*XS_STRIDE + k0]);
            #pragma unroll
            for (int i = 0; i < 4; i++)
                #pragma unroll
                for (int jj = 0; jj < 2; jj++){
                    c01[i][jj] += xv[i].x*av[jj].x;
                    c01[i][jj] += xv[i].y*av[jj].y;
                    c01[i][jj] += xv[i].z*av[jj].z;
                    c01[i][jj] += xv[i].w*av[jj].w;
                }
        }
        #pragma unroll
        for (int i = 0; i < 4; i++){
            int t = t0 + ty*4 + i;
            #pragma unroll
            for (int jj = 0; jj < 2; jj++){
                int sl = tx + 32*jj;
                Ps[(ty*4+i)*PS_STRIDE + sl] = c01[i][jj] * g_Chat[t*N + s0 + sl];
            }
        }
    }
    __syncthreads();

    // ---- phase 2: Y_partial = P @ G ----
    const float* Psrc = isW ? (Xs + (b-NB)*SC) : Ps;
    int pstride = isW ? XS_STRIDE : PS_STRIDE;

    float y[4][4];
    #pragma unroll
    for (int i = 0; i < 4; i++)
        #pragma unroll
        for (int jj = 0; jj < 4; jj++) y[i][jj] = 0.f;

    #pragma unroll 4
    for (int s = 0; s < SC; s += 4){
        float4 p[4], g[4];
        #pragma unroll
        for (int i = 0; i < 4; i++)
            p[i] = *reinterpret_cast<const float4*>(&Psrc[(ty*4+i)*pstride + s]);
        #pragma unroll
        for (int ss = 0; ss < 4; ss++)
            g[ss] = *reinterpret_cast<const float4*>(&Gs[(s+ss)*XS_STRIDE + tx*4]);
        #pragma unroll
        for (int i = 0; i < 4; i++){
            y[i][0] += p[i].x*g[0].x + p[i].y*g[1].x + p[i].z*g[2].x + p[i].w*g[3].x;
            y[i][1] += p[i].x*g[0].y + p[i].y*g[1].y + p[i].z*g[2].y + p[i].w*g[3].y;
            y[i][2] += p[i].x*g[0].z + p[i].y*g[1].z + p[i].z*g[2].z + p[i].w*g[3].z;
            y[i][3] += p[i].x*g[0].w + p[i].y*g[1].w + p[i].z*g[2].w + p[i].w*g[3].w;
        }
    }
    #pragma unroll
    for (int i = 0; i < 4; i++){
        float4 v; v.x=y[i][0]; v.y=y[i][1]; v.z=y[i][2]; v.w=y[i][3];
        *reinterpret_cast<float4*>(&Ydst[((b*N) + t0 + ty*4 + i)*D + tx*4]) = v;
    }
}

// ---------------- finalize: sum final partial slices ----------------
__global__ void finalize_kernel(float* __restrict__ out){
    int e = blockIdx.x*blockDim.x + threadIdx.x;
    int t = e >> 7, j = e & 127;
    int rb = (t >> 6) + 1;
    float a = g_Yp1[(8*N + t)*D + j] + g_Yp1[(9*N + t)*D + j];
    for (int c = 0; c < rb; c++) a += g_Yp1[(c*N + t)*D + j];
    out[e] = a;
}

// ---------------- launch ----------------
extern "C" void kernel_launch(void* const* d_in, const int* in_sizes, int n_in,
                              void* d_out, int out_size){
    const float* seq    = (const float*)d_in[0];
    const float* Wmem   = (const float*)d_in[1];
    const float* Wq     = (const float*)d_in[2];
    const float* Wkv    = (const float*)d_in[3];
    const float* Wmom   = (const float*)d_in[4];
    const float* Wstep  = (const float*)d_in[5];
    const float* Wdecay = (const float*)d_in[6];
    float* out = (float*)d_out;

    size_t smem = (size_t)(TT*XS_STRIDE + 2*SC*XS_STRIDE + TT*PS_STRIDE)*sizeof(float); // 93184
    cudaFuncSetAttribute(layer_kernel, cudaFuncAttributeMaxDynamicSharedMemorySize, (int)smem);

    tr_kernel<<<DEPTH, 128>>>(Wmem);
    token_kernel<<<N/4, 128>>>(seq, Wmem, Wq, Wkv, Wmom, Wstep, Wdecay);
    chat_kernel<<<1, N>>>();

    dim3 lg(NA, NSLICE);
    layer_kernel<<<lg, 256, smem>>>(Wmem, 0, 0);   // q   -> Yp0
    layer_kernel<<<lg, 256, smem>>>(Wmem, 1, 1);   // Yp0 -> Yp1
    layer_kernel<<<lg, 256, smem>>>(Wmem, 2, 2);   // Yp1 -> Yp0
    layer_kernel<<<lg, 256, smem>>>(Wmem, 3, 1);   // Yp0 -> Yp1
    finalize_kernel<<<(N*D)/256, 256>>>(out);
}

// round 3
// speedup vs baseline: 2.0259x; 1.2869x over previous
#include <cuda_runtime.h>
#include <math.h>

#define N 512
#define D 128
#define DEPTH 4
#define TT 32
#define SC 32
#define NREAL 136        // triangular real (a,b) pairs, b<=a, a<16
#define NBLK 200         // 136 real + 64 W-chunk blocks
#define NSLICE 20        // 16 real s-chunk slices + 4 W slices
#define STR 132
#define PSTR 36

// ---------------- scratch ----------------
__device__ float g_q[N*D];
__device__ float g_X[N*D];
__device__ float g_lr[N], g_am[N], g_dk[N];
__device__ float g_A[DEPTH*N*D];
__device__ float g_G[DEPTH*N*D];
__device__ float g_WT[DEPTH*D*D];
__device__ float g_Chat[N*N];
__device__ float g_Yp[NSLICE*N*D];

__device__ __forceinline__ float siluf(float z){
    float s = 1.f/(1.f+__expf(-z));
    return z*s;
}
__device__ __forceinline__ float dsiluf(float z){
    float s = 1.f/(1.f+__expf(-z));
    return s*(1.f + z*(1.f-s));
}

// ---------------- transpose W_mem ----------------
__global__ void tr_kernel(const float* __restrict__ Wmem){
    int l = blockIdx.x;
    for (int e = threadIdx.x; e < D*D; e += blockDim.x){
        int j = e >> 7, i = e & 127;
        g_WT[l*D*D + e] = Wmem[l*D*D + i*D + j];
    }
}

// ---------------- helper: 4-token GEMV with unroll-8 weight stream ----------------
__device__ __forceinline__ void gemv4(const float sxa[4][D], const float* __restrict__ Wp,
                                      int j, float z[4]){
    z[0]=0.f; z[1]=0.f; z[2]=0.f; z[3]=0.f;
    for (int i = 0; i < D; i += 8){
        float w[8];
        #pragma unroll
        for (int u = 0; u < 8; u++) w[u] = Wp[(i+u)*D + j];
        #pragma unroll
        for (int m = 0; m < 4; m++){
            float4 xa = *reinterpret_cast<const float4*>(&sxa[m][i]);
            float4 xb = *reinterpret_cast<const float4*>(&sxa[m][i+4]);
            z[m] += xa.x*w[0] + xa.y*w[1] + xa.z*w[2] + xa.w*w[3]
                  + xb.x*w[4] + xb.y*w[5] + xb.z*w[6] + xb.w*w[7];
        }
    }
}

// ---------------- per-token MLP fwd+bwd, 4 tokens per block ----------------
__global__ __launch_bounds__(128) void token_kernel(const float* __restrict__ seq,
                             const float* __restrict__ Wmem,
                             const float* __restrict__ Wq,
                             const float* __restrict__ Wkv,
                             const float* __restrict__ Wmom,
                             const float* __restrict__ Wstep,
                             const float* __restrict__ Wdecay){
    int t0 = blockIdx.x*4;
    int j = threadIdx.x;
    __shared__ float sx[4][D];
    __shared__ float sA[4][D];
    __shared__ float sB[4][D];
    __shared__ float sv[4][D];
    __shared__ float red[12][4];

    #pragma unroll
    for (int m = 0; m < 4; m++) sx[m][j] = seq[(t0+m)*D + j];

    // per-token scalars
    {
        float ws = Wstep[j], wm = Wmom[j], wd = Wdecay[j];
        #pragma unroll
        for (int m = 0; m < 4; m++){
            float xv = sx[m][j];
            float p0 = xv*ws, p1 = xv*wm, p2 = xv*wd;
            #pragma unroll
            for (int o = 16; o > 0; o >>= 1){
                p0 += __shfl_xor_sync(0xffffffffu, p0, o);
                p1 += __shfl_xor_sync(0xffffffffu, p1, o);
                p2 += __shfl_xor_sync(0xffffffffu, p2, o);
            }
            if ((j & 31) == 0){ red[m*3+0][j>>5]=p0; red[m*3+1][j>>5]=p1; red[m*3+2][j>>5]=p2; }
        }
    }
    __syncthreads();
    if (j < 4){
        g_lr[t0+j] = red[j*3+0][0]+red[j*3+0][1]+red[j*3+0][2]+red[j*3+0][3];
        g_am[t0+j] = red[j*3+1][0]+red[j*3+1][1]+red[j*3+1][2]+red[j*3+1][3];
        float dz = red[j*3+2][0]+red[j*3+2][1]+red[j*3+2][2]+red[j*3+2][3];
        g_dk[t0+j] = 1.f - 1.f/(1.f+__expf(-dz));
    }

    // q, k, v (3 weight streams -> MLP ~12)
    {
        float qa[4]={0,0,0,0}, ka[4]={0,0,0,0}, va[4]={0,0,0,0};
        for (int i = 0; i < D; i += 4){
            float4 xm[4];
            #pragma unroll
            for (int m = 0; m < 4; m++) xm[m] = *reinterpret_cast<const float4*>(&sx[m][i]);
            #pragma unroll
            for (int ii = 0; ii < 4; ii++){
                float wqv = Wq[(i+ii)*D + j];
                float wkv = Wkv[(i+ii)*2*D + j];
                float wvv = Wkv[(i+ii)*2*D + D + j];
                #pragma unroll
                for (int m = 0; m < 4; m++){
                    float xv = (ii==0)?xm[m].x:(ii==1)?xm[m].y:(ii==2)?xm[m].z:xm[m].w;
                    qa[m] += xv*wqv; ka[m] += xv*wkv; va[m] += xv*wvv;
                }
            }
        }
        #pragma unroll
        for (int m = 0; m < 4; m++){
            g_q[(t0+m)*D + j] = qa[m];
            g_A[0*N*D + (t0+m)*D + j] = ka[m];
            sA[m][j] = ka[m]; sv[m][j] = va[m];
        }
    }
    __syncthreads();

    float z1[4], z2[4], z3[4], z[4];

    gemv4(sA, Wmem + 0*D*D, j, z);                  // z1 = k @ W0
    #pragma unroll
    for (int m = 0; m < 4; m++){
        z1[m]=z[m]; float x1=siluf(z[m]);
        sB[m][j]=x1; g_A[1*N*D + (t0+m)*D + j]=x1;
    }
    __syncthreads();

    gemv4(sB, Wmem + 1*D*D, j, z);                  // z2 = x1 @ W1
    #pragma unroll
    for (int m = 0; m < 4; m++){
        z2[m]=z[m]; float x2=siluf(z[m]);
        sA[m][j]=x2; g_A[2*N*D + (t0+m)*D + j]=x2;
    }
    __syncthreads();

    gemv4(sA, Wmem + 2*D*D, j, z);                  // z3 = x2 @ W2
    #pragma unroll
    for (int m = 0; m < 4; m++){
        z3[m]=z[m]; float x3=siluf(z[m]);
        sB[m][j]=x3; g_A[3*N*D + (t0+m)*D + j]=x3;
    }
    __syncthreads();

    gemv4(sB, Wmem + 3*D*D, j, z);                  // z4 = x3 @ W3
    #pragma unroll
    for (int m = 0; m < 4; m++){
        float gg = (z[m] - sv[m][j]) * (2.f/(float)D);
        sA[m][j]=gg; g_G[3*N*D + (t0+m)*D + j]=gg;
    }
    __syncthreads();

    gemv4(sA, g_WT + 3*D*D, j, z);                  // dx = g3 @ W3^T
    #pragma unroll
    for (int m = 0; m < 4; m++){
        float gg = z[m]*dsiluf(z3[m]);
        sB[m][j]=gg; g_G[2*N*D + (t0+m)*D + j]=gg;
    }
    __syncthreads();

    gemv4(sB, g_WT + 2*D*D, j, z);                  // dx = g2 @ W2^T
    #pragma unroll
    for (int m = 0; m < 4; m++){
        float gg = z[m]*dsiluf(z2[m]);
        sA[m][j]=gg; g_G[1*N*D + (t0+m)*D + j]=gg;
    }
    __syncthreads();

    gemv4(sA, g_WT + 1*D*D, j, z);                  // dx = g1 @ W1^T
    #pragma unroll
    for (int m = 0; m < 4; m++)
        g_G[0*N*D + (t0+m)*D + j] = z[m]*dsiluf(z1[m]);
}

// ---------------- scan-coefficient matrix ----------------
__global__ void chat_kernel(){
    __shared__ float sam[N], sdk[N];
    int s = threadIdx.x;
    sam[s] = g_am[s]; sdk[s] = g_dk[s];
    __syncthreads();
    float m = 0.f, c = 0.f;
    float nl = -g_lr[s];
    for (int t = 0; t < N; t++){
        float out;
        if (t < s) out = 0.f;
        else if (t == s){ m = 1.f; c = 1.f; out = nl; }
        else {
            m *= sam[t];
            c = sdk[t]*c + m;
            out = nl*c;
        }
        g_Chat[t*N + s] = out;
    }
}

// ---------------- fused attention layer ----------------
// Flattened grid of exactly NBLK active blocks.
// id < NREAL: real (a,b) with b<=a (triangular). Else: W-chunk (a = q>>2, wc = q&3).
__global__ __launch_bounds__(256) void layer_kernel(const float* __restrict__ Wmem,
                                                    int layer, int first){
    extern __shared__ float sm[];
    float* Xs = sm;                 // [TT][STR]
    float* As = Xs + TT*STR;        // [SC][STR]
    float* Gs = As + SC*STR;        // [SC][STR]
    float* Ps = Gs + SC*STR;        // [TT][PSTR]

    int id = blockIdx.x;
    int a, b; bool isW;
    if (id < NREAL){
        int r = id; a = 0;
        while (r > a){ r -= a + 1; a++; }
        b = r; isW = false;
    } else {
        int q = id - NREAL; a = q >> 2; b = q & 3; isW = true;
    }
    int t0 = a*TT;
    int tid = threadIdx.x, tx = tid & 31, ty = tid >> 5;

    const float* Xsrc = first ? g_q : g_X;
    for (int e = tid; e < TT*32; e += 256){
        int t = e >> 5, k4 = (e & 31)*4;
        *reinterpret_cast<float4*>(&Xs[t*STR + k4]) =
            *reinterpret_cast<const float4*>(&Xsrc[(t0+t)*D + k4]);
    }
    if (!isW){
        const float* Al = g_A + layer*N*D;
        const float* Gl = g_G + layer*N*D;
        int s0 = b*SC;
        for (int e = tid; e < SC*32; e += 256){
            int r = e >> 5, k4 = (e & 31)*4;
            *reinterpret_cast<float4*>(&As[r*STR + k4]) =
                *reinterpret_cast<const float4*>(&Al[(s0+r)*D + k4]);
        }
        for (int e = tid; e < SC*32; e += 256){
            int r = e >> 5, k4 = (e & 31)*4;
            *reinterpret_cast<float4*>(&Gs[r*STR + k4]) =
                *reinterpret_cast<const float4*>(&Gl[(s0+r)*D + k4]);
        }
    } else {
        const float* Wl = Wmem + layer*D*D;
        int w0 = b*SC;
        for (int e = tid; e < SC*32; e += 256){
            int r = e >> 5, k4 = (e & 31)*4;
            *reinterpret_cast<float4*>(&Gs[r*STR + k4]) =
                *reinterpret_cast<const float4*>(&Wl[(w0+r)*D + k4]);
        }
    }
    __syncthreads();

    // ---- phase 1 (real blocks): S = (X @ A^T) ⊙ Chat -> Ps ----
    if (!isW){
        int s0 = b*SC;
        float c0=0.f, c1=0.f, c2=0.f, c3=0.f;
        const float* ar = As + tx*STR;
        #pragma unroll 4
        for (int k = 0; k < D; k += 4){
            float4 av = *reinterpret_cast<const float4*>(&ar[k]);
            float4 x0 = *reinterpret_cast<const float4*>(&Xs[(ty*4+0)*STR + k]);
            float4 x1 = *reinterpret_cast<const float4*>(&Xs[(ty*4+1)*STR + k]);
            float4 x2 = *reinterpret_cast<const float4*>(&Xs[(ty*4+2)*STR + k]);
            float4 x3 = *reinterpret_cast<const float4*>(&Xs[(ty*4+3)*STR + k]);
            c0 += x0.x*av.x + x0.y*av.y + x0.z*av.z + x0.w*av.w;
            c1 += x1.x*av.x + x1.y*av.y + x1.z*av.z + x1.w*av.w;
            c2 += x2.x*av.x + x2.y*av.y + x2.z*av.z + x2.w*av.w;
            c3 += x3.x*av.x + x3.y*av.y + x3.z*av.z + x3.w*av.w;
        }
        int sg = s0 + tx;
        Ps[(ty*4+0)*PSTR + tx] = c0 * g_Chat[(t0+ty*4+0)*N + sg];
        Ps[(ty*4+1)*PSTR + tx] = c1 * g_Chat[(t0+ty*4+1)*N + sg];
        Ps[(ty*4+2)*PSTR + tx] = c2 * g_Chat[(t0+ty*4+2)*N + sg];
        Ps[(ty*4+3)*PSTR + tx] = c3 * g_Chat[(t0+ty*4+3)*N + sg];
    }
    __syncthreads();

    // ---- phase 2: Y_slice = P @ G ----
    const float* Psrc = isW ? (Xs + b*SC) : Ps;
    int pst = isW ? STR : PSTR;

    float y[4][4];
    #pragma unroll
    for (int i = 0; i < 4; i++)
        #pragma unroll
        for (int jj = 0; jj < 4; jj++) y[i][jj] = 0.f;

    #pragma unroll 4
    for (int s = 0; s < SC; s += 4){
        float4 g0 = *reinterpret_cast<const float4*>(&Gs[(s+0)*STR + tx*4]);
        float4 g1 = *reinterpret_cast<const float4*>(&Gs[(s+1)*STR + tx*4]);
        float4 g2 = *reinterpret_cast<const float4*>(&Gs[(s+2)*STR + tx*4]);
        float4 g3 = *reinterpret_cast<const float4*>(&Gs[(s+3)*STR + tx*4]);
        #pragma unroll
        for (int i = 0; i < 4; i++){
            float4 p = *reinterpret_cast<const float4*>(&Psrc[(ty*4+i)*pst + s]);
            y[i][0] += p.x*g0.x + p.y*g1.x + p.z*g2.x + p.w*g3.x;
            y[i][1] += p.x*g0.y + p.y*g1.y + p.z*g2.y + p.w*g3.y;
            y[i][2] += p.x*g0.z + p.y*g1.z + p.z*g2.z + p.w*g3.z;
            y[i][3] += p.x*g0.w + p.y*g1.w + p.z*g2.w + p.w*g3.w;
        }
    }
    int slice = isW ? (16 + b) : b;
    #pragma unroll
    for (int i = 0; i < 4; i++){
        float4 v; v.x=y[i][0]; v.y=y[i][1]; v.z=y[i][2]; v.w=y[i][3];
        *reinterpret_cast<float4*>(&g_Yp[((slice*N) + t0 + ty*4 + i)*D + tx*4]) = v;
    }
}

// ---------------- reduce slices (+silu) between layers; last -> out ----------------
__global__ void reduce_kernel(float* __restrict__ out, int last){
    int idx = blockIdx.x*blockDim.x + threadIdx.x;
    int t = idx >> 7, j = idx & 127;
    int nr = (t >> 5) + 1;
    float acc = g_Yp[(16*N + t)*D + j] + g_Yp[(17*N + t)*D + j]
              + g_Yp[(18*N + t)*D + j] + g_Yp[(19*N + t)*D + j];
    for (int c = 0; c < nr; c++) acc += g_Yp[(c*N + t)*D + j];
    if (last) out[idx] = acc;
    else      g_X[idx] = siluf(acc);
}

// ---------------- launch ----------------
extern "C" void kernel_launch(void* const* d_in, const int* in_sizes, int n_in,
                              void* d_out, int out_size){
    const float* seq    = (const float*)d_in[0];
    const float* Wmem   = (const float*)d_in[1];
    const float* Wq     = (const float*)d_in[2];
    const float* Wkv    = (const float*)d_in[3];
    const float* Wmom   = (const float*)d_in[4];
    const float* Wstep  = (const float*)d_in[5];
    const float* Wdecay = (const float*)d_in[6];
    float* out = (float*)d_out;

    size_t smem = (size_t)(TT*STR + 2*SC*STR + TT*PSTR)*sizeof(float);   // 55296 B
    cudaFuncSetAttribute(layer_kernel, cudaFuncAttributeMaxDynamicSharedMemorySize, (int)smem);

    tr_kernel<<<DEPTH, 128>>>(Wmem);
    token_kernel<<<N/4, 128>>>(seq, Wmem, Wq, Wkv, Wmom, Wstep, Wdecay);
    chat_kernel<<<1, N>>>();

    layer_kernel<<<NBLK, 256, smem>>>(Wmem, 0, 1);
    reduce_kernel<<<(N*D)/256, 256>>>(out, 0);
    layer_kernel<<<NBLK, 256, smem>>>(Wmem, 1, 0);
    reduce_kernel<<<(N*D)/256, 256>>>(out, 0);
    layer_kernel<<<NBLK, 256, smem>>>(Wmem, 2, 0);
    reduce_kernel<<<(N*D)/256, 256>>>(out, 0);
    layer_kernel<<<NBLK, 256, smem>>>(Wmem, 3, 0);
    reduce_kernel<<<(N*D)/256, 256>>>(out, 1);
}

// round 4
// speedup vs baseline: 2.3113x; 1.1409x over previous
#include <cuda_runtime.h>
#include <math.h>

#define N 512
#define D 128
#define DEPTH 4
#define TT 16
#define SC 32
#define NREAL 272        // sum over a=0..31 of (a/2 + 1)
#define NBLK 400         // 272 real + 128 W blocks
#define NSLICE 20        // 16 real s-chunk slices + 4 W slices
#define XSTR 132
#define ASTR 33
#define GSTR 132
#define PSTR 36

// ---------------- scratch ----------------
__device__ float g_q[N*D];
__device__ float g_X[N*D];
__device__ float g_lr[N], g_am[N], g_dk[N];
__device__ float g_A[DEPTH*N*D];
__device__ float g_G[DEPTH*N*D];
__device__ float g_WT[DEPTH*D*D];
__device__ float g_Chat[N*N];
__device__ float g_Yp[NSLICE*N*D];

__device__ __forceinline__ float siluf(float z){
    float s = 1.f/(1.f+__expf(-z));
    return z*s;
}
__device__ __forceinline__ float dsiluf(float z){
    float s = 1.f/(1.f+__expf(-z));
    return s*(1.f + z*(1.f-s));
}

// ---------------- transpose W_mem ----------------
__global__ void tr_kernel(const float* __restrict__ Wmem){
    int l = blockIdx.x;
    for (int e = threadIdx.x; e < D*D; e += blockDim.x){
        int j = e >> 7, i = e & 127;
        g_WT[l*D*D + e] = Wmem[l*D*D + i*D + j];
    }
}

// ---------------- half-GEMV: 4 tokens, 64 i's, unroll 16 ----------------
__device__ __forceinline__ void gemv4h(const float sxa[4][D], const float* __restrict__ Wp,
                                       int j, int h, float z[4]){
    const float* W = Wp + (h*64)*D + j;
    z[0]=0.f; z[1]=0.f; z[2]=0.f; z[3]=0.f;
    const int base = h*64;
    for (int i = 0; i < 64; i += 16){
        float w[16];
        #pragma unroll
        for (int u = 0; u < 16; u++) w[u] = W[(i+u)*D];
        #pragma unroll
        for (int m = 0; m < 4; m++){
            const float* xr = &sxa[m][base+i];
            float4 x0 = *reinterpret_cast<const float4*>(&xr[0]);
            float4 x1 = *reinterpret_cast<const float4*>(&xr[4]);
            float4 x2 = *reinterpret_cast<const float4*>(&xr[8]);
            float4 x3 = *reinterpret_cast<const float4*>(&xr[12]);
            z[m] += x0.x*w[0]+x0.y*w[1]+x0.z*w[2]+x0.w*w[3]
                  + x1.x*w[4]+x1.y*w[5]+x1.z*w[6]+x1.w*w[7]
                  + x2.x*w[8]+x2.y*w[9]+x2.z*w[10]+x2.w*w[11]
                  + x3.x*w[12]+x3.y*w[13]+x3.z*w[14]+x3.w*w[15];
        }
    }
}

// ---------------- per-token MLP fwd+bwd: 4 tokens/block, 256 thr (i split in half) ----------------
__global__ __launch_bounds__(256) void token_kernel(const float* __restrict__ seq,
                             const float* __restrict__ Wmem,
                             const float* __restrict__ Wq,
                             const float* __restrict__ Wkv,
                             const float* __restrict__ Wmom,
                             const float* __restrict__ Wstep,
                             const float* __restrict__ Wdecay){
    int t0 = blockIdx.x*4;
    int tid = threadIdx.x;
    int j = tid & 127;
    int h = tid >> 7;
    __shared__ float sx[4][D];
    __shared__ float sA[4][D];
    __shared__ float sB[4][D];
    __shared__ float sv[4][D];
    __shared__ float szp[3][2][4][D];
    __shared__ float red[12][4];

    for (int e = tid; e < 4*D; e += 256){
        int m = e >> 7, jj = e & 127;
        sx[m][jj] = seq[(t0+m)*D + jj];
    }
    __syncthreads();

    // per-token scalars (first half only)
    if (h == 0){
        float ws = Wstep[j], wm = Wmom[j], wd = Wdecay[j];
        #pragma unroll
        for (int m = 0; m < 4; m++){
            float xv = sx[m][j];
            float p0 = xv*ws, p1 = xv*wm, p2 = xv*wd;
            #pragma unroll
            for (int o = 16; o > 0; o >>= 1){
                p0 += __shfl_xor_sync(0xffffffffu, p0, o);
                p1 += __shfl_xor_sync(0xffffffffu, p1, o);
                p2 += __shfl_xor_sync(0xffffffffu, p2, o);
            }
            if ((j & 31) == 0){ red[m*3+0][j>>5]=p0; red[m*3+1][j>>5]=p1; red[m*3+2][j>>5]=p2; }
        }
    }

    // q,k,v partials (3 weight streams over this thread's i-half)
    {
        float qa[4]={0,0,0,0}, ka[4]={0,0,0,0}, va[4]={0,0,0,0};
        const float* Wqh  = Wq  + (h*64)*D + j;
        const float* Wkh  = Wkv + (h*64)*2*D + j;
        const float* Wvh  = Wkv + (h*64)*2*D + D + j;
        const int base = h*64;
        for (int i = 0; i < 64; i += 8){
            float wq[8], wk[8], wv[8];
            #pragma unroll
            for (int u = 0; u < 8; u++){
                wq[u] = Wqh[(i+u)*D];
                wk[u] = Wkh[(i+u)*2*D];
                wv[u] = Wvh[(i+u)*2*D];
            }
            #pragma unroll
            for (int m = 0; m < 4; m++){
                const float* xr = &sx[m][base+i];
                float4 xa = *reinterpret_cast<const float4*>(&xr[0]);
                float4 xb = *reinterpret_cast<const float4*>(&xr[4]);
                qa[m] += xa.x*wq[0]+xa.y*wq[1]+xa.z*wq[2]+xa.w*wq[3]
                       + xb.x*wq[4]+xb.y*wq[5]+xb.z*wq[6]+xb.w*wq[7];
                ka[m] += xa.x*wk[0]+xa.y*wk[1]+xa.z*wk[2]+xa.w*wk[3]
                       + xb.x*wk[4]+xb.y*wk[5]+xb.z*wk[6]+xb.w*wk[7];
                va[m] += xa.x*wv[0]+xa.y*wv[1]+xa.z*wv[2]+xa.w*wv[3]
                       + xb.x*wv[4]+xb.y*wv[5]+xb.z*wv[6]+xb.w*wv[7];
            }
        }
        #pragma unroll
        for (int m = 0; m < 4; m++){
            szp[0][h][m][j] = qa[m];
            szp[1][h][m][j] = ka[m];
            szp[2][h][m][j] = va[m];
        }
    }
    __syncthreads();
    if (h == 0){
        if (j < 4){
            g_lr[t0+j] = red[j*3+0][0]+red[j*3+0][1]+red[j*3+0][2]+red[j*3+0][3];
            g_am[t0+j] = red[j*3+1][0]+red[j*3+1][1]+red[j*3+1][2]+red[j*3+1][3];
            float dz = red[j*3+2][0]+red[j*3+2][1]+red[j*3+2][2]+red[j*3+2][3];
            g_dk[t0+j] = 1.f - 1.f/(1.f+__expf(-dz));
        }
        #pragma unroll
        for (int m = 0; m < 4; m++){
            g_q[(t0+m)*D + j] = szp[0][0][m][j] + szp[0][1][m][j];
            float kk = szp[1][0][m][j] + szp[1][1][m][j];
            sA[m][j] = kk; g_A[0*N*D + (t0+m)*D + j] = kk;
            sv[m][j] = szp[2][0][m][j] + szp[2][1][m][j];
        }
    }
    __syncthreads();

    float z1[4], z2[4], z3[4], zp[4], z[4];

    // stage 1: z1 = k @ W0
    gemv4h(sA, Wmem + 0*D*D, j, h, zp);
    #pragma unroll
    for (int m = 0; m < 4; m++) szp[0][h][m][j] = zp[m];
    __syncthreads();
    #pragma unroll
    for (int m = 0; m < 4; m++){
        z[m] = szp[0][0][m][j] + szp[0][1][m][j]; z1[m] = z[m];
        if (h == 0){ float x1 = siluf(z[m]); sB[m][j] = x1; g_A[1*N*D + (t0+m)*D + j] = x1; }
    }
    __syncthreads();

    // stage 2: z2 = x1 @ W1
    gemv4h(sB, Wmem + 1*D*D, j, h, zp);
    #pragma unroll
    for (int m = 0; m < 4; m++) szp[0][h][m][j] = zp[m];
    __syncthreads();
    #pragma unroll
    for (int m = 0; m < 4; m++){
        z[m] = szp[0][0][m][j] + szp[0][1][m][j]; z2[m] = z[m];
        if (h == 0){ float x2 = siluf(z[m]); sA[m][j] = x2; g_A[2*N*D + (t0+m)*D + j] = x2; }
    }
    __syncthreads();

    // stage 3: z3 = x2 @ W2
    gemv4h(sA, Wmem + 2*D*D, j, h, zp);
    #pragma unroll
    for (int m = 0; m < 4; m++) szp[0][h][m][j] = zp[m];
    __syncthreads();
    #pragma unroll
    for (int m = 0; m < 4; m++){
        z[m] = szp[0][0][m][j] + szp[0][1][m][j]; z3[m] = z[m];
        if (h == 0){ float x3 = siluf(z[m]); sB[m][j] = x3; g_A[3*N*D + (t0+m)*D + j] = x3; }
    }
    __syncthreads();

    // stage 4: z4 = x3 @ W3 ; g3
    gemv4h(sB, Wmem + 3*D*D, j, h, zp);
    #pragma unroll
    for (int m = 0; m < 4; m++) szp[0][h][m][j] = zp[m];
    __syncthreads();
    #pragma unroll
    for (int m = 0; m < 4; m++){
        z[m] = szp[0][0][m][j] + szp[0][1][m][j];
        if (h == 0){
            float gg = (z[m] - sv[m][j]) * (2.f/(float)D);
            sA[m][j] = gg; g_G[3*N*D + (t0+m)*D + j] = gg;
        }
    }
    __syncthreads();

    // bwd stage: g2
    gemv4h(sA, g_WT + 3*D*D, j, h, zp);
    #pragma unroll
    for (int m = 0; m < 4; m++) szp[0][h][m][j] = zp[m];
    __syncthreads();
    #pragma unroll
    for (int m = 0; m < 4; m++){
        z[m] = szp[0][0][m][j] + szp[0][1][m][j];
        if (h == 0){
            float gg = z[m]*dsiluf(z3[m]);
            sB[m][j] = gg; g_G[2*N*D + (t0+m)*D + j] = gg;
        }
    }
    __syncthreads();

    // bwd stage: g1
    gemv4h(sB, g_WT + 2*D*D, j, h, zp);
    #pragma unroll
    for (int m = 0; m < 4; m++) szp[0][h][m][j] = zp[m];
    __syncthreads();
    #pragma unroll
    for (int m = 0; m < 4; m++){
        z[m] = szp[0][0][m][j] + szp[0][1][m][j];
        if (h == 0){
            float gg = z[m]*dsiluf(z2[m]);
            sA[m][j] = gg; g_G[1*N*D + (t0+m)*D + j] = gg;
        }
    }
    __syncthreads();

    // bwd stage: g0
    gemv4h(sA, g_WT + 1*D*D, j, h, zp);
    #pragma unroll
    for (int m = 0; m < 4; m++) szp[0][h][m][j] = zp[m];
    __syncthreads();
    if (h == 0){
        #pragma unroll
        for (int m = 0; m < 4; m++){
            float zz = szp[0][0][m][j] + szp[0][1][m][j];
            g_G[0*N*D + (t0+m)*D + j] = zz*dsiluf(z1[m]);
        }
    }
}

// ---------------- scan-coefficient matrix (parallel over s) ----------------
__global__ void chat_kernel(){
    __shared__ float sam[N], sdk[N];
    int s = blockIdx.x*128 + threadIdx.x;
    for (int i = threadIdx.x; i < N; i += 128){ sam[i] = g_am[i]; sdk[i] = g_dk[i]; }
    __syncthreads();
    float m = 0.f, c = 0.f;
    float nl = -g_lr[s];
    for (int t = 0; t < N; t++){
        float out;
        if (t < s) out = 0.f;
        else if (t == s){ m = 1.f; c = 1.f; out = nl; }
        else {
            m *= sam[t];
            c = sdk[t]*c + m;
            out = nl*c;
        }
        g_Chat[t*N + s] = out;
    }
}

// ---------------- fused attention layer ----------------
__global__ __launch_bounds__(128) void layer_kernel(const float* __restrict__ Wmem,
                                                    int layer, int first){
    extern __shared__ float sm[];
    float* Xs  = sm;                  // [TT][XSTR]
    float* AsT = Xs + TT*XSTR;        // [D][ASTR] transposed A chunk
    float* Gs  = AsT + D*ASTR;        // [SC][GSTR]
    float* Ps  = Gs + SC*GSTR;        // [TT][PSTR]

    int id = blockIdx.x;
    int a, b; bool isW;
    if (id < NREAL){
        int r = id; a = 0;
        for (;;){ int c = (a >> 1) + 1; if (r < c) break; r -= c; a++; }
        b = r; isW = false;
    } else {
        int q = id - NREAL; a = q >> 2; b = q & 3; isW = true;
    }
    int t0 = a*TT;
    int tid = threadIdx.x, tx = tid & 31, ty = tid >> 5;

    const float* Xsrc = first ? g_q : g_X;
    for (int e = tid; e < TT*32; e += 128){
        int t = e >> 5, k4 = (e & 31)*4;
        *reinterpret_cast<float4*>(&Xs[t*XSTR + k4]) =
            *reinterpret_cast<const float4*>(&Xsrc[(t0+t)*D + k4]);
    }
    if (!isW){
        const float* Al = g_A + layer*N*D;
        const float* Gl = g_G + layer*N*D;
        int s0 = b*SC;
        for (int e = tid; e < SC*32; e += 128){
            int r = e >> 5, k4 = (e & 31)*4;
            float4 v = *reinterpret_cast<const float4*>(&Al[(s0+r)*D + k4]);
            AsT[(k4+0)*ASTR + r] = v.x;
            AsT[(k4+1)*ASTR + r] = v.y;
            AsT[(k4+2)*ASTR + r] = v.z;
            AsT[(k4+3)*ASTR + r] = v.w;
        }
        for (int e = tid; e < SC*32; e += 128){
            int r = e >> 5, k4 = (e & 31)*4;
            *reinterpret_cast<float4*>(&Gs[r*GSTR + k4]) =
                *reinterpret_cast<const float4*>(&Gl[(s0+r)*D + k4]);
        }
    } else {
        const float* Wl = Wmem + layer*D*D;
        int w0 = b*SC;
        for (int e = tid; e < SC*32; e += 128){
            int r = e >> 5, k4 = (e & 31)*4;
            *reinterpret_cast<float4*>(&Gs[r*GSTR + k4]) =
                *reinterpret_cast<const float4*>(&Wl[(w0+r)*D + k4]);
        }
    }
    __syncthreads();

    // ---- phase 1 (real): S = (X @ A^T) ⊙ Chat -> Ps ----
    if (!isW){
        int s0 = b*SC;
        float c0=0.f, c1=0.f, c2=0.f, c3=0.f;
        #pragma unroll 8
        for (int k = 0; k < D; k += 4){
            float a0 = AsT[(k+0)*ASTR + tx];
            float a1 = AsT[(k+1)*ASTR + tx];
            float a2 = AsT[(k+2)*ASTR + tx];
            float a3 = AsT[(k+3)*ASTR + tx];
            float4 x0 = *reinterpret_cast<const float4*>(&Xs[(ty*4+0)*XSTR + k]);
            float4 x1 = *reinterpret_cast<const float4*>(&Xs[(ty*4+1)*XSTR + k]);
            float4 x2 = *reinterpret_cast<const float4*>(&Xs[(ty*4+2)*XSTR + k]);
            float4 x3 = *reinterpret_cast<const float4*>(&Xs[(ty*4+3)*XSTR + k]);
            c0 += x0.x*a0 + x0.y*a1 + x0.z*a2 + x0.w*a3;
            c1 += x1.x*a0 + x1.y*a1 + x1.z*a2 + x1.w*a3;
            c2 += x2.x*a0 + x2.y*a1 + x2.z*a2 + x2.w*a3;
            c3 += x3.x*a0 + x3.y*a1 + x3.z*a2 + x3.w*a3;
        }
        int sg = s0 + tx;
        Ps[(ty*4+0)*PSTR + tx] = c0 * g_Chat[(t0+ty*4+0)*N + sg];
        Ps[(ty*4+1)*PSTR + tx] = c1 * g_Chat[(t0+ty*4+1)*N + sg];
        Ps[(ty*4+2)*PSTR + tx] = c2 * g_Chat[(t0+ty*4+2)*N + sg];
        Ps[(ty*4+3)*PSTR + tx] = c3 * g_Chat[(t0+ty*4+3)*N + sg];
    }
    __syncthreads();

    // ---- phase 2: Y_slice = P @ G ----
    const float* Psrc = isW ? (Xs + b*SC) : Ps;
    int pst = isW ? XSTR : PSTR;

    float y[4][4];
    #pragma unroll
    for (int i = 0; i < 4; i++)
        #pragma unroll
        for (int jj = 0; jj < 4; jj++) y[i][jj] = 0.f;

    #pragma unroll 4
    for (int s = 0; s < SC; s += 4){
        float4 g0 = *reinterpret_cast<const float4*>(&Gs[(s+0)*GSTR + tx*4]);
        float4 g1 = *reinterpret_cast<const float4*>(&Gs[(s+1)*GSTR + tx*4]);
        float4 g2 = *reinterpret_cast<const float4*>(&Gs[(s+2)*GSTR + tx*4]);
        float4 g3 = *reinterpret_cast<const float4*>(&Gs[(s+3)*GSTR + tx*4]);
        #pragma unroll
        for (int i = 0; i < 4; i++){
            float4 p = *reinterpret_cast<const float4*>(&Psrc[(ty*4+i)*pst + s]);
            y[i][0] += p.x*g0.x + p.y*g1.x + p.z*g2.x + p.w*g3.x;
            y[i][1] += p.x*g0.y + p.y*g1.y + p.z*g2.y + p.w*g3.y;
            y[i][2] += p.x*g0.z + p.y*g1.z + p.z*g2.z + p.w*g3.z;
            y[i][3] += p.x*g0.w + p.y*g1.w + p.z*g2.w + p.w*g3.w;
        }
    }
    int slice = isW ? (16 + b) : b;
    #pragma unroll
    for (int i = 0; i < 4; i++){
        float4 v; v.x=y[i][0]; v.y=y[i][1]; v.z=y[i][2]; v.w=y[i][3];
        *reinterpret_cast<float4*>(&g_Yp[((slice*N) + t0 + ty*4 + i)*D + tx*4]) = v;
    }
}

// ---------------- reduce slices (+silu) between layers; last -> out ----------------
__global__ void reduce_kernel(float* __restrict__ out, int last){
    int idx = blockIdx.x*blockDim.x + threadIdx.x;
    int t = idx >> 7, j = idx & 127;
    int nr = (t >> 5) + 1;
    float acc = g_Yp[(16*N + t)*D + j] + g_Yp[(17*N + t)*D + j]
              + g_Yp[(18*N + t)*D + j] + g_Yp[(19*N + t)*D + j];
    for (int c = 0; c < nr; c++) acc += g_Yp[(c*N + t)*D + j];
    if (last) out[idx] = acc;
    else      g_X[idx] = siluf(acc);
}

// ---------------- launch ----------------
extern "C" void kernel_launch(void* const* d_in, const int* in_sizes, int n_in,
                              void* d_out, int out_size){
    const float* seq    = (const float*)d_in[0];
    const float* Wmem   = (const float*)d_in[1];
    const float* Wq     = (const float*)d_in[2];
    const float* Wkv    = (const float*)d_in[3];
    const float* Wmom   = (const float*)d_in[4];
    const float* Wstep  = (const float*)d_in[5];
    const float* Wdecay = (const float*)d_in[6];
    float* out = (float*)d_out;

    size_t smem = (size_t)(TT*XSTR + D*ASTR + SC*GSTR + TT*PSTR)*sizeof(float);  // 44544 B
    cudaFuncSetAttribute(layer_kernel, cudaFuncAttributeMaxDynamicSharedMemorySize, (int)smem);

    tr_kernel<<<DEPTH, 128>>>(Wmem);
    token_kernel<<<N/4, 256>>>(seq, Wmem, Wq, Wkv, Wmom, Wstep, Wdecay);
    chat_kernel<<<4, 128>>>();

    layer_kernel<<<NBLK, 128, smem>>>(Wmem, 0, 1);
    reduce_kernel<<<(N*D)/256, 256>>>(out, 0);
    layer_kernel<<<NBLK, 128, smem>>>(Wmem, 1, 0);
    reduce_kernel<<<(N*D)/256, 256>>>(out, 0);
    layer_kernel<<<NBLK, 128, smem>>>(Wmem, 2, 0);
    reduce_kernel<<<(N*D)/256, 256>>>(out, 0);
    layer_kernel<<<NBLK, 128, smem>>>(Wmem, 3, 0);
    reduce_kernel<<<(N*D)/256, 256>>>(out, 1);
}

// round 5
// speedup vs baseline: 2.5042x; 1.0835x over previous
#include <cuda_runtime.h>
#include <math.h>

#define N 512
#define D 128
#define DEPTH 4
#define TT 32
#define SC 32
#define NREAL 136        // triangular (a,b), b<=a, a<16
#define NBLK 200         // 136 real + 64 W blocks
#define NSLICE 20
#define STR 132
#define PSTR 36
#define CSTR 36

// ---------------- scratch ----------------
__device__ float g_q[N*D];
__device__ float g_X[N*D];
__device__ float g_lr[N], g_am[N], g_dk[N];
__device__ float g_A[DEPTH*N*D];
__device__ float g_G[DEPTH*N*D];
__device__ float g_WT[DEPTH*D*D];
__device__ float g_Chat[N*N];
__device__ float g_Yp[NSLICE*N*D];

__device__ __forceinline__ float siluf(float z){
    float s = 1.f/(1.f+__expf(-z));
    return z*s;
}
__device__ __forceinline__ float dsiluf(float z){
    float s = 1.f/(1.f+__expf(-z));
    return s*(1.f + z*(1.f-s));
}

// ---------------- transpose W_mem ----------------
__global__ void tr_kernel(const float* __restrict__ Wmem){
    int l = blockIdx.x;
    for (int e = threadIdx.x; e < D*D; e += blockDim.x){
        int j = e >> 7, i = e & 127;
        g_WT[l*D*D + e] = Wmem[l*D*D + i*D + j];
    }
}

// ---------------- half-GEMV: 4 tokens, 64 i's, unroll 32 ----------------
__device__ __forceinline__ void gemv4h(const float sxa[4][D], const float* __restrict__ Wp,
                                       int j, int h, float z[4]){
    const float* W = Wp + (h*64)*D + j;
    z[0]=0.f; z[1]=0.f; z[2]=0.f; z[3]=0.f;
    const int base = h*64;
    #pragma unroll
    for (int i = 0; i < 64; i += 32){
        float w[32];
        #pragma unroll
        for (int u = 0; u < 32; u++) w[u] = W[(i+u)*D];
        #pragma unroll
        for (int m = 0; m < 4; m++){
            const float* xr = &sxa[m][base+i];
            float acc = 0.f;
            #pragma unroll
            for (int q = 0; q < 32; q += 4){
                float4 x = *reinterpret_cast<const float4*>(&xr[q]);
                acc += x.x*w[q] + x.y*w[q+1] + x.z*w[q+2] + x.w*w[q+3];
            }
            z[m] += acc;
        }
    }
}

// ---------------- per-token MLP fwd+bwd: 4 tokens/block, 256 thr ----------------
__global__ __launch_bounds__(256) void token_kernel(const float* __restrict__ seq,
                             const float* __restrict__ Wmem,
                             const float* __restrict__ Wq,
                             const float* __restrict__ Wkv,
                             const float* __restrict__ Wmom,
                             const float* __restrict__ Wstep,
                             const float* __restrict__ Wdecay){
    int t0 = blockIdx.x*4;
    int tid = threadIdx.x;
    int j = tid & 127;
    int h = tid >> 7;
    __shared__ float sx[4][D];
    __shared__ float sA[4][D];
    __shared__ float sB[4][D];
    __shared__ float sv[4][D];
    __shared__ float szp[3][2][4][D];
    __shared__ float red[12][4];

    for (int e = tid; e < 4*D; e += 256){
        int m = e >> 7, jj = e & 127;
        sx[m][jj] = seq[(t0+m)*D + jj];
    }
    __syncthreads();

    if (h == 0){
        float ws = Wstep[j], wm = Wmom[j], wd = Wdecay[j];
        #pragma unroll
        for (int m = 0; m < 4; m++){
            float xv = sx[m][j];
            float p0 = xv*ws, p1 = xv*wm, p2 = xv*wd;
            #pragma unroll
            for (int o = 16; o > 0; o >>= 1){
                p0 += __shfl_xor_sync(0xffffffffu, p0, o);
                p1 += __shfl_xor_sync(0xffffffffu, p1, o);
                p2 += __shfl_xor_sync(0xffffffffu, p2, o);
            }
            if ((j & 31) == 0){ red[m*3+0][j>>5]=p0; red[m*3+1][j>>5]=p1; red[m*3+2][j>>5]=p2; }
        }
    }

    // q,k,v partials
    {
        float qa[4]={0,0,0,0}, ka[4]={0,0,0,0}, va[4]={0,0,0,0};
        const float* Wqh  = Wq  + (h*64)*D + j;
        const float* Wkh  = Wkv + (h*64)*2*D + j;
        const float* Wvh  = Wkv + (h*64)*2*D + D + j;
        const int base = h*64;
        for (int i = 0; i < 64; i += 8){
            float wq[8], wk[8], wv[8];
            #pragma unroll
            for (int u = 0; u < 8; u++){
                wq[u] = Wqh[(i+u)*D];
                wk[u] = Wkh[(i+u)*2*D];
                wv[u] = Wvh[(i+u)*2*D];
            }
            #pragma unroll
            for (int m = 0; m < 4; m++){
                const float* xr = &sx[m][base+i];
                float4 xa = *reinterpret_cast<const float4*>(&xr[0]);
                float4 xb = *reinterpret_cast<const float4*>(&xr[4]);
                qa[m] += xa.x*wq[0]+xa.y*wq[1]+xa.z*wq[2]+xa.w*wq[3]
                       + xb.x*wq[4]+xb.y*wq[5]+xb.z*wq[6]+xb.w*wq[7];
                ka[m] += xa.x*wk[0]+xa.y*wk[1]+xa.z*wk[2]+xa.w*wk[3]
                       + xb.x*wk[4]+xb.y*wk[5]+xb.z*wk[6]+xb.w*wk[7];
                va[m] += xa.x*wv[0]+xa.y*wv[1]+xa.z*wv[2]+xa.w*wv[3]
                       + xb.x*wv[4]+xb.y*wv[5]+xb.z*wv[6]+xb.w*wv[7];
            }
        }
        #pragma unroll
        for (int m = 0; m < 4; m++){
            szp[0][h][m][j] = qa[m];
            szp[1][h][m][j] = ka[m];
            szp[2][h][m][j] = va[m];
        }
    }
    __syncthreads();
    if (h == 0){
        if (j < 4){
            g_lr[t0+j] = red[j*3+0][0]+red[j*3+0][1]+red[j*3+0][2]+red[j*3+0][3];
            g_am[t0+j] = red[j*3+1][0]+red[j*3+1][1]+red[j*3+1][2]+red[j*3+1][3];
            float dz = red[j*3+2][0]+red[j*3+2][1]+red[j*3+2][2]+red[j*3+2][3];
            g_dk[t0+j] = 1.f - 1.f/(1.f+__expf(-dz));
        }
        #pragma unroll
        for (int m = 0; m < 4; m++){
            g_q[(t0+m)*D + j] = szp[0][0][m][j] + szp[0][1][m][j];
            float kk = szp[1][0][m][j] + szp[1][1][m][j];
            sA[m][j] = kk; g_A[0*N*D + (t0+m)*D + j] = kk;
            sv[m][j] = szp[2][0][m][j] + szp[2][1][m][j];
        }
    }
    __syncthreads();

    float z1[4], z2[4], z3[4], zp[4], z[4];

    gemv4h(sA, Wmem + 0*D*D, j, h, zp);
    #pragma unroll
    for (int m = 0; m < 4; m++) szp[0][h][m][j] = zp[m];
    __syncthreads();
    #pragma unroll
    for (int m = 0; m < 4; m++){
        z[m] = szp[0][0][m][j] + szp[0][1][m][j]; z1[m] = z[m];
        if (h == 0){ float x1 = siluf(z[m]); sB[m][j] = x1; g_A[1*N*D + (t0+m)*D + j] = x1; }
    }
    __syncthreads();

    gemv4h(sB, Wmem + 1*D*D, j, h, zp);
    #pragma unroll
    for (int m = 0; m < 4; m++) szp[0][h][m][j] = zp[m];
    __syncthreads();
    #pragma unroll
    for (int m = 0; m < 4; m++){
        z[m] = szp[0][0][m][j] + szp[0][1][m][j]; z2[m] = z[m];
        if (h == 0){ float x2 = siluf(z[m]); sA[m][j] = x2; g_A[2*N*D + (t0+m)*D + j] = x2; }
    }
    __syncthreads();

    gemv4h(sA, Wmem + 2*D*D, j, h, zp);
    #pragma unroll
    for (int m = 0; m < 4; m++) szp[0][h][m][j] = zp[m];
    __syncthreads();
    #pragma unroll
    for (int m = 0; m < 4; m++){
        z[m] = szp[0][0][m][j] + szp[0][1][m][j]; z3[m] = z[m];
        if (h == 0){ float x3 = siluf(z[m]); sB[m][j] = x3; g_A[3*N*D + (t0+m)*D + j] = x3; }
    }
    __syncthreads();

    gemv4h(sB, Wmem + 3*D*D, j, h, zp);
    #pragma unroll
    for (int m = 0; m < 4; m++) szp[0][h][m][j] = zp[m];
    __syncthreads();
    #pragma unroll
    for (int m = 0; m < 4; m++){
        z[m] = szp[0][0][m][j] + szp[0][1][m][j];
        if (h == 0){
            float gg = (z[m] - sv[m][j]) * (2.f/(float)D);
            sA[m][j] = gg; g_G[3*N*D + (t0+m)*D + j] = gg;
        }
    }
    __syncthreads();

    gemv4h(sA, g_WT + 3*D*D, j, h, zp);
    #pragma unroll
    for (int m = 0; m < 4; m++) szp[0][h][m][j] = zp[m];
    __syncthreads();
    #pragma unroll
    for (int m = 0; m < 4; m++){
        z[m] = szp[0][0][m][j] + szp[0][1][m][j];
        if (h == 0){
            float gg = z[m]*dsiluf(z3[m]);
            sB[m][j] = gg; g_G[2*N*D + (t0+m)*D + j] = gg;
        }
    }
    __syncthreads();

    gemv4h(sB, g_WT + 2*D*D, j, h, zp);
    #pragma unroll
    for (int m = 0; m < 4; m++) szp[0][h][m][j] = zp[m];
    __syncthreads();
    #pragma unroll
    for (int m = 0; m < 4; m++){
        z[m] = szp[0][0][m][j] + szp[0][1][m][j];
        if (h == 0){
            float gg = z[m]*dsiluf(z2[m]);
            sA[m][j] = gg; g_G[1*N*D + (t0+m)*D + j] = gg;
        }
    }
    __syncthreads();

    gemv4h(sA, g_WT + 1*D*D, j, h, zp);
    #pragma unroll
    for (int m = 0; m < 4; m++) szp[0][h][m][j] = zp[m];
    __syncthreads();
    if (h == 0){
        #pragma unroll
        for (int m = 0; m < 4; m++){
            float zz = szp[0][0][m][j] + szp[0][1][m][j];
            g_G[0*N*D + (t0+m)*D + j] = zz*dsiluf(z1[m]);
        }
    }
}

// ---------------- scan-coefficient matrix (parallel over s) ----------------
__global__ void chat_kernel(){
    __shared__ float sam[N], sdk[N];
    int s = blockIdx.x*128 + threadIdx.x;
    for (int i = threadIdx.x; i < N; i += 128){ sam[i] = g_am[i]; sdk[i] = g_dk[i]; }
    __syncthreads();
    float m = 0.f, c = 0.f;
    float nl = -g_lr[s];
    for (int t = 0; t < N; t++){
        float out;
        if (t < s) out = 0.f;
        else if (t == s){ m = 1.f; c = 1.f; out = nl; }
        else {
            m *= sam[t];
            c = sdk[t]*c + m;
            out = nl*c;
        }
        g_Chat[t*N + s] = out;
    }
}

// ---------------- fused attention layer ----------------
__global__ __launch_bounds__(256) void layer_kernel(const float* __restrict__ Wmem,
                                                    int layer, int first){
    extern __shared__ float sm[];
    float* Xs = sm;                 // [TT][STR]
    float* As = Xs + TT*STR;        // [SC][STR]
    float* Gs = As + SC*STR;        // [SC][STR]
    float* Cs = Gs + SC*STR;        // [TT][CSTR]
    float* Ps = Cs + TT*CSTR;       // [TT][PSTR]

    int id = blockIdx.x;
    int a, b; bool isW;
    if (id < NREAL){
        int r = id; a = 0;
        while (r > a){ r -= a + 1; a++; }
        b = r; isW = false;
    } else {
        int q = id - NREAL; a = q >> 2; b = q & 3; isW = true;
    }
    int t0 = a*TT;
    int tid = threadIdx.x, tx = tid & 31, ty = tid >> 5;

    const float* Xsrc = first ? g_q : g_X;
    for (int e = tid; e < TT*32; e += 256){
        int t = e >> 5, k4 = (e & 31)*4;
        *reinterpret_cast<float4*>(&Xs[t*STR + k4]) =
            *reinterpret_cast<const float4*>(&Xsrc[(t0+t)*D + k4]);
    }
    if (!isW){
        const float* Al = g_A + layer*N*D;
        const float* Gl = g_G + layer*N*D;
        int s0 = b*SC;
        for (int e = tid; e < SC*32; e += 256){
            int r = e >> 5, k4 = (e & 31)*4;
            *reinterpret_cast<float4*>(&As[r*STR + k4]) =
                *reinterpret_cast<const float4*>(&Al[(s0+r)*D + k4]);
        }
        for (int e = tid; e < SC*32; e += 256){
            int r = e >> 5, k4 = (e & 31)*4;
            *reinterpret_cast<float4*>(&Gs[r*STR + k4]) =
                *reinterpret_cast<const float4*>(&Gl[(s0+r)*D + k4]);
        }
        // Chat tile [TT][SC] -> Cs
        for (int e = tid; e < TT*8; e += 256){
            int t = e >> 3, s4 = (e & 7)*4;
            *reinterpret_cast<float4*>(&Cs[t*CSTR + s4]) =
                *reinterpret_cast<const float4*>(&g_Chat[(t0+t)*N + s0 + s4]);
        }
    } else {
        const float* Wl = Wmem + layer*D*D;
        int w0 = b*SC;
        for (int e = tid; e < SC*32; e += 256){
            int r = e >> 5, k4 = (e & 31)*4;
            *reinterpret_cast<float4*>(&Gs[r*STR + k4]) =
                *reinterpret_cast<const float4*>(&Wl[(w0+r)*D + k4]);
        }
    }
    __syncthreads();

    // ---- phase 1 (real): S = (X @ A^T) ⊙ Chat -> Ps ----
    if (!isW){
        float c0=0.f, c1=0.f, c2=0.f, c3=0.f;
        const float* ar = As + tx*STR;
        const float* x0r = Xs + (ty*4+0)*STR;
        const float* x1r = Xs + (ty*4+1)*STR;
        const float* x2r = Xs + (ty*4+2)*STR;
        const float* x3r = Xs + (ty*4+3)*STR;
        #pragma unroll 8
        for (int k = 0; k < D; k += 4){
            float4 av = *reinterpret_cast<const float4*>(&ar[k]);
            float4 x0 = *reinterpret_cast<const float4*>(&x0r[k]);
            float4 x1 = *reinterpret_cast<const float4*>(&x1r[k]);
            float4 x2 = *reinterpret_cast<const float4*>(&x2r[k]);
            float4 x3 = *reinterpret_cast<const float4*>(&x3r[k]);
            c0 += x0.x*av.x + x0.y*av.y + x0.z*av.z + x0.w*av.w;
            c1 += x1.x*av.x + x1.y*av.y + x1.z*av.z + x1.w*av.w;
            c2 += x2.x*av.x + x2.y*av.y + x2.z*av.z + x2.w*av.w;
            c3 += x3.x*av.x + x3.y*av.y + x3.z*av.z + x3.w*av.w;
        }
        Ps[(ty*4+0)*PSTR + tx] = c0 * Cs[(ty*4+0)*CSTR + tx];
        Ps[(ty*4+1)*PSTR + tx] = c1 * Cs[(ty*4+1)*CSTR + tx];
        Ps[(ty*4+2)*PSTR + tx] = c2 * Cs[(ty*4+2)*CSTR + tx];
        Ps[(ty*4+3)*PSTR + tx] = c3 * Cs[(ty*4+3)*CSTR + tx];
    }
    __syncthreads();

    // ---- phase 2: Y_slice = P @ G ----
    const float* Psrc = isW ? (Xs + b*SC) : Ps;
    int pst = isW ? STR : PSTR;

    float y[4][4];
    #pragma unroll
    for (int i = 0; i < 4; i++)
        #pragma unroll
        for (int jj = 0; jj < 4; jj++) y[i][jj] = 0.f;

    #pragma unroll 4
    for (int s = 0; s < SC; s += 4){
        float4 g0 = *reinterpret_cast<const float4*>(&Gs[(s+0)*STR + tx*4]);
        float4 g1 = *reinterpret_cast<const float4*>(&Gs[(s+1)*STR + tx*4]);
        float4 g2 = *reinterpret_cast<const float4*>(&Gs[(s+2)*STR + tx*4]);
        float4 g3 = *reinterpret_cast<const float4*>(&Gs[(s+3)*STR + tx*4]);
        #pragma unroll
        for (int i = 0; i < 4; i++){
            float4 p = *reinterpret_cast<const float4*>(&Psrc[(ty*4+i)*pst + s]);
            y[i][0] += p.x*g0.x + p.y*g1.x + p.z*g2.x + p.w*g3.x;
            y[i][1] += p.x*g0.y + p.y*g1.y + p.z*g2.y + p.w*g3.y;
            y[i][2] += p.x*g0.z + p.y*g1.z + p.z*g2.z + p.w*g3.z;
            y[i][3] += p.x*g0.w + p.y*g1.w + p.z*g2.w + p.w*g3.w;
        }
    }
    int slice = isW ? (16 + b) : b;
    #pragma unroll
    for (int i = 0; i < 4; i++){
        float4 v; v.x=y[i][0]; v.y=y[i][1]; v.z=y[i][2]; v.w=y[i][3];
        *reinterpret_cast<float4*>(&g_Yp[((slice*N) + t0 + ty*4 + i)*D + tx*4]) = v;
    }
}

// ---------------- reduce slices (+silu) between layers; last -> out ----------------
__global__ void reduce_kernel(float* __restrict__ out, int last){
    int idx = blockIdx.x*blockDim.x + threadIdx.x;
    int t = idx >> 7, j = idx & 127;
    int nr = (t >> 5) + 1;
    float acc = g_Yp[(16*N + t)*D + j] + g_Yp[(17*N + t)*D + j]
              + g_Yp[(18*N + t)*D + j] + g_Yp[(19*N + t)*D + j];
    for (int c = 0; c < nr; c++) acc += g_Yp[(c*N + t)*D + j];
    if (last) out[idx] = acc;
    else      g_X[idx] = siluf(acc);
}

// ---------------- launch ----------------
extern "C" void kernel_launch(void* const* d_in, const int* in_sizes, int n_in,
                              void* d_out, int out_size){
    const float* seq    = (const float*)d_in[0];
    const float* Wmem   = (const float*)d_in[1];
    const float* Wq     = (const float*)d_in[2];
    const float* Wkv    = (const float*)d_in[3];
    const float* Wmom   = (const float*)d_in[4];
    const float* Wstep  = (const float*)d_in[5];
    const float* Wdecay = (const float*)d_in[6];
    float* out = (float*)d_out;

    size_t smem = (size_t)(TT*STR + 2*SC*STR + TT*CSTR + TT*PSTR)*sizeof(float); // ~59.9KB
    cudaFuncSetAttribute(layer_kernel, cudaFuncAttributeMaxDynamicSharedMemorySize, (int)smem);

    tr_kernel<<<DEPTH, 128>>>(Wmem);
    token_kernel<<<N/4, 256>>>(seq, Wmem, Wq, Wkv, Wmom, Wstep, Wdecay);
    chat_kernel<<<4, 128>>>();

    layer_kernel<<<NBLK, 256, smem>>>(Wmem, 0, 1);
    reduce_kernel<<<(N*D)/256, 256>>>(out, 0);
    layer_kernel<<<NBLK, 256, smem>>>(Wmem, 1, 0);
    reduce_kernel<<<(N*D)/256, 256>>>(out, 0);
    layer_kernel<<<NBLK, 256, smem>>>(Wmem, 2, 0);
    reduce_kernel<<<(N*D)/256, 256>>>(out, 0);
    layer_kernel<<<NBLK, 256, smem>>>(Wmem, 3, 0);
    reduce_kernel<<<(N*D)/256, 256>>>(out, 1);
}